// round 12
// baseline (speedup 1.0000x reference)
#include <cuda_runtime.h>
#include <cuda.h>
#include <cuda_fp16.h>
#include <math.h>
#include <stdint.h>

// Problem dims
#define T_STEPS 128
#define BB      256
#define DIN     1024
#define HH      1024
#define NQ      8
#define DD      2048
#define NC      4112          // zf|zi|g|o|basef(8)|basei(8)
#define NPAD    4224          // 33 tiles of 128
#define NCTA    132

// ---------------- persistent device scratch ----------------
__device__ float g_Wall[(size_t)NC * DD];
__device__ float g_ball[NPAD];
__device__ __align__(256) __half g_Bp[(size_t)NPAD * 2048];         // [Wx|Wh] fp16, K-contig
__device__ __align__(256) __half g_Xp[(size_t)T_STEPS * BB * 1024]; // fp16(X)
__device__ __align__(256) __half g_Hp[(size_t)BB * 1024];           // fp16(hx)
__device__ float g_CT[(size_t)NPAD * BB];                           // C^T [n][b] (+bias)
__device__ float g_CXT[HH * BB];                                    // cell state [h][b]
__device__ unsigned long long g_bar = 0;

// ============================================================
// GEMM: block 64(M) x 128(N), 8 gemm warps (2Mx4N), warp 32x32,
// K=2048 ([X|H] source switch), BK=64, 3-stage cp.async.
// ============================================================
#define APITCH  72
#define A_ST    (64 * APITCH * 2)        // 9216
#define B_ST    (128 * APITCH * 2)       // 18432
#define STG_B   (A_ST + B_ST)            // 27648
#define GSMEM   (3 * STG_B)              // 82944
#define NTL     32                        // 2048/64

__device__ __forceinline__ uint32_t smem_u32(const void* p) {
    uint32_t a;
    asm("{ .reg .u64 t; cvta.to.shared.u64 t, %1; cvt.u32.u64 %0, t; }" : "=r"(a) : "l"(p));
    return a;
}
__device__ __forceinline__ void cp_async16(uint32_t dst, const void* src) {
    asm volatile("cp.async.cg.shared.global [%0], [%1], 16;" :: "r"(dst), "l"(src));
}
__device__ __forceinline__ void ldmatrix_x4(uint32_t& r0, uint32_t& r1,
                                            uint32_t& r2, uint32_t& r3, uint32_t a) {
    asm volatile("ldmatrix.sync.aligned.m8n8.x4.shared.b16 {%0,%1,%2,%3}, [%4];"
                 : "=r"(r0), "=r"(r1), "=r"(r2), "=r"(r3) : "r"(a));
}
__device__ __forceinline__ void mma_f16(float* c, const uint32_t* a,
                                        uint32_t b0, uint32_t b1) {
    asm volatile("mma.sync.aligned.m16n8k16.row.col.f32.f16.f16.f32 "
                 "{%0,%1,%2,%3}, {%4,%5,%6,%7}, {%8,%9}, {%0,%1,%2,%3};"
                 : "+f"(c[0]), "+f"(c[1]), "+f"(c[2]), "+f"(c[3])
                 : "r"(a[0]), "r"(a[1]), "r"(a[2]), "r"(a[3]), "r"(b0), "r"(b1));
}
#define GBAR_WARPS() asm volatile("bar.sync 1, 256;" ::: "memory")

__device__ __forceinline__ float sigf(float x) {
    float e = __expf(-x);
    return __fdividef(1.f, 1.f + e);
}

// One step GEMM: C^T[n0:n0+128][m0:m0+64] = [x|h] @ W^T + bias  (tid<256 only)
__device__ __forceinline__ void gemm_k2048(const __half* __restrict__ xp,
                                           int m0, int n0, uint32_t sb, int tid)
{
    const int lane = tid & 31, wid = tid >> 5;
    const int wm = wid & 1, wn = wid >> 1;

    // A load: 4 threads/row, each 2x16B -> cols (tid&3)*16 .. +16
    const int arow = tid >> 2, acol = (tid & 3) * 16;
    const uint32_t daB = sb + (arow * APITCH + acol) * 2;
    // B load: 2 threads/row, each 4x16B -> cols (tid&1)*32 + j*8
    const int brow = tid >> 1, bcol = (tid & 1) * 32;
    const __half* gB = g_Bp + (size_t)(n0 + brow) * 2048 + bcol;
    const uint32_t dbB = sb + A_ST + (brow * APITCH + bcol) * 2;

    auto issue = [&](int kt, int st) {
        const __half* asrc = (kt < 16) ? xp : g_Hp;
        const int kc = (kt & 15) * 64;
        const __half* ga = asrc + (size_t)(m0 + arow) * 1024 + kc + acol;
        const uint32_t da = daB + st * STG_B;
        cp_async16(da, ga);
        cp_async16(da + 16, ga + 8);
        const __half* gb = gB + kt * 64;
        const uint32_t db = dbB + st * STG_B;
#pragma unroll
        for (int j = 0; j < 4; j++) cp_async16(db + j * 16, gb + j * 8);
    };

    float acc[2][4][4];
#pragma unroll
    for (int i = 0; i < 2; i++)
#pragma unroll
        for (int j = 0; j < 4; j++)
#pragma unroll
            for (int r = 0; r < 4; r++) acc[i][j][r] = 0.f;

    const uint32_t aA0 = sb + ((wm * 32 + (lane & 15)) * APITCH + (lane >> 4) * 8) * 2;
    const int brl = wn * 32 + (lane & 7) + ((lane >> 4) << 3);
    const uint32_t bA0 = sb + A_ST + (brl * APITCH + ((lane >> 3) & 1) * 8) * 2;

#pragma unroll
    for (int s = 0; s < 2; s++) {
        issue(s, s);
        asm volatile("cp.async.commit_group;");
    }

    for (int kt = 0; kt < NTL; kt++) {
        asm volatile("cp.async.wait_group 1;");
        GBAR_WARPS();
        if (kt + 2 < NTL) issue(kt + 2, (kt + 2) % 3);
        asm volatile("cp.async.commit_group;");

        const int st = kt % 3;
        const uint32_t aB = aA0 + st * STG_B;
        const uint32_t bB = bA0 + st * STG_B;
#pragma unroll
        for (int kk = 0; kk < 4; kk++) {
            uint32_t a[2][4], b[2][4];
#pragma unroll
            for (int mf = 0; mf < 2; mf++)
                ldmatrix_x4(a[mf][0], a[mf][1], a[mf][2], a[mf][3],
                            aB + (mf * 16 * APITCH + kk * 16) * 2);
#pragma unroll
            for (int nf = 0; nf < 2; nf++)
                ldmatrix_x4(b[nf][0], b[nf][1], b[nf][2], b[nf][3],
                            bB + (nf * 16 * APITCH + kk * 16) * 2);
#pragma unroll
            for (int mf = 0; mf < 2; mf++)
#pragma unroll
                for (int nf = 0; nf < 2; nf++) {
                    mma_f16(acc[mf][nf * 2 + 0], a[mf], b[nf][0], b[nf][1]);
                    mma_f16(acc[mf][nf * 2 + 1], a[mf], b[nf][2], b[nf][3]);
                }
        }
    }

#pragma unroll
    for (int mf = 0; mf < 2; mf++) {
        const int mb = m0 + wm * 32 + mf * 16 + (lane >> 2);
#pragma unroll
        for (int j = 0; j < 4; j++) {
            const int nb = n0 + wn * 32 + j * 8 + 2 * (lane & 3);
            const float b0 = __ldg(&g_ball[nb]), b1 = __ldg(&g_ball[nb + 1]);
            g_CT[(size_t)nb * BB + mb]           = acc[mf][j][0] + b0;
            g_CT[(size_t)(nb + 1) * BB + mb]     = acc[mf][j][1] + b1;
            g_CT[(size_t)nb * BB + mb + 8]       = acc[mf][j][2] + b0;
            g_CT[(size_t)(nb + 1) * BB + mb + 8] = acc[mf][j][3] + b1;
        }
    }
}

__device__ __forceinline__ void grid_bar(int tid) {
    __syncthreads();
    if (tid == 0) {
        __threadfence();
        unsigned long long t0 = atomicAdd(&g_bar, 1ULL);
        unsigned long long tgt = (t0 / (unsigned long long)NCTA + 1ULL) * (unsigned long long)NCTA;
        while (*((volatile unsigned long long*)&g_bar) < tgt) { __nanosleep(32); }
        __threadfence();
    }
    __syncthreads();
}

// ============================================================
// Persistent kernel: 384 threads; tid<256 do GEMM, all do elem
// ============================================================
__global__ __launch_bounds__(384, 1) void persist_kernel(
    float* __restrict__ out,
    const float* __restrict__ wfw, const float* __restrict__ wfb,
    const float* __restrict__ wiw, const float* __restrict__ wib)
{
    extern __shared__ __align__(16) char smraw[];
    const uint32_t sb = smem_u32(smraw);
    const int tid = threadIdx.x;
    const int n0 = blockIdx.x * 128, m0 = blockIdx.y * 64;
    const int cta = blockIdx.y * 33 + blockIdx.x;

    for (int t = 0; t < T_STEPS; t++) {
        // Phase G: full-K GEMM for step t
        if (tid < 256)
            gemm_k2048(g_Xp + (size_t)t * BB * 1024, m0, n0, sb, tid);
        grid_bar(tid);

        // Phase E: gates/wire/state with all 384 threads
        float* out_t = out + (size_t)t * BB * HH;
#pragma unroll 1
        for (int k = 0; k < 6; k++) {
            int id = cta * 384 + tid + k * (NCTA * 384);
            if (id >= BB * HH) break;
            int h = id >> 8, b = id & 255;
            auto rd = [&](int n) { return g_CT[(size_t)n * BB + b]; };
            float f_pre, i_pre;
            if (h < NQ) {
                float df[NQ], di[NQ];
                f_pre = 0.f; i_pre = 0.f;
#pragma unroll
                for (int i = 0; i < NQ; i++) {
                    float dot = rd(4096 + i) + __ldg(&wfb[i]);
#pragma unroll
                    for (int kk = 0; kk < NQ; kk++)
                        if (kk < i) dot += df[kk] * __ldg(&wfw[i * 1024 + kk]);
                    float v = tanhf(dot);
                    df[i] = v - rd(i);
                    if (i == h) f_pre = v;
                }
#pragma unroll
                for (int i = 0; i < NQ; i++) {
                    float dot = rd(4104 + i) + __ldg(&wib[i]);
#pragma unroll
                    for (int kk = 0; kk < NQ; kk++)
                        if (kk < i) dot += di[kk] * __ldg(&wiw[i * 1024 + kk]);
                    float v = tanhf(dot);
                    di[i] = v - rd(1024 + i);
                    if (i == h) i_pre = v;
                }
            } else {
                f_pre = rd(h);
                i_pre = rd(1024 + h);
            }
            const float gg = tanhf(rd(2048 + h));
            const float o  = sigf(rd(3072 + h));
            const size_t p = (size_t)h * BB + b;
            const float c = sigf(f_pre) * g_CXT[p] + sigf(i_pre) * gg;
            g_CXT[p] = c;
            const float hv = o * tanhf(c);
            out_t[(size_t)b * HH + h] = hv;
            g_Hp[(size_t)b * 1024 + h] = __float2half(hv);
        }
        grid_bar(tid);
    }
}

// ============================================================
// prep kernels
// ============================================================
#define BM 64
#define BN 128
#define BK 16
__global__ __launch_bounds__(256) void gemm_generic(
    const float* __restrict__ A, int sA,
    const float* __restrict__ Bm, int sBn, int sBk,
    float* __restrict__ C, int ldc, int M, int N, int K)
{
    __shared__ float Ash[BK][BM + 1];
    __shared__ float Bsh[BK][BN + 1];
    int tid = threadIdx.x, tx = tid & 15, ty = tid >> 4;
    int m0 = blockIdx.y * BM, n0 = blockIdx.x * BN;
    float acc[4][8];
#pragma unroll
    for (int i = 0; i < 4; i++)
#pragma unroll
        for (int j = 0; j < 8; j++) acc[i][j] = 0.f;
    for (int k0 = 0; k0 < K; k0 += BK) {
#pragma unroll
        for (int r = 0; r < 4; r++) {
            int ml = ty + 16 * r, mm = m0 + ml;
            Ash[tx][ml] = (mm < M) ? A[(size_t)mm * sA + k0 + tx] : 0.f;
        }
#pragma unroll
        for (int r = 0; r < 8; r++) {
            int nl = ty + 16 * r, nn = n0 + nl;
            Bsh[tx][nl] = (nn < N) ? Bm[(size_t)nn * sBn + (size_t)(k0 + tx) * sBk] : 0.f;
        }
        __syncthreads();
#pragma unroll
        for (int kk = 0; kk < BK; kk++) {
            float a[4], b[8];
#pragma unroll
            for (int i = 0; i < 4; i++) a[i] = Ash[kk][ty + 16 * i];
#pragma unroll
            for (int j = 0; j < 8; j++) b[j] = Bsh[kk][tx + 16 * j];
#pragma unroll
            for (int i = 0; i < 4; i++)
#pragma unroll
                for (int j = 0; j < 8; j++) acc[i][j] += a[i] * b[j];
        }
        __syncthreads();
    }
#pragma unroll
    for (int i = 0; i < 4; i++) {
        int mm = m0 + ty + 16 * i;
        if (mm >= M) continue;
#pragma unroll
        for (int j = 0; j < 8; j++) {
            int nn = n0 + tx + 16 * j;
            if (nn < N) C[(size_t)mm * ldc + nn] = acc[i][j];
        }
    }
}

__global__ void zero_cx_kernel() {
    int idx = blockIdx.x * blockDim.x + threadIdx.x;
    if (idx < HH * BB) g_CXT[idx] = 0.f;
}
__global__ void zero_hp_kernel() {
    int idx = blockIdx.x * blockDim.x + threadIdx.x;
    if (idx < BB * 1024) g_Hp[idx] = __float2half(0.f);
}
__global__ void copy_wuwo_kernel(const float* __restrict__ Wu, const float* __restrict__ Wo) {
    size_t idx = (size_t)blockIdx.x * blockDim.x + threadIdx.x;
    size_t total = (size_t)2 * 1024 * DD;
    if (idx < total) {
        float v = (idx < (size_t)1024 * DD) ? Wu[idx] : Wo[idx - (size_t)1024 * DD];
        g_Wall[(size_t)2048 * DD + idx] = v;
    }
}
__global__ void bias_enc_kernel(const float* __restrict__ encf, const float* __restrict__ enci,
                                const float* __restrict__ bq)
{
    int w = (blockIdx.x * blockDim.x + threadIdx.x) >> 5;
    int lane = threadIdx.x & 31;
    if (w >= 2048) return;
    const float* enc = (w < 1024) ? encf : enci;
    int row = w & 1023;
    float s = 0.f;
    for (int j = lane; j < 1024; j += 32) s += enc[row * 1024 + j] * bq[j];
#pragma unroll
    for (int o = 16; o > 0; o >>= 1) s += __shfl_xor_sync(0xFFFFFFFF, s, o);
    if (lane == 0) g_ball[w] = s;
}
__global__ void bias_copy_kernel(const float* __restrict__ bu, const float* __restrict__ bo) {
    int n = 2048 + blockIdx.x * blockDim.x + threadIdx.x;
    if (n < 3072) g_ball[n] = bu[n - 2048];
    else if (n < 4096) g_ball[n] = bo[n - 3072];
    else if (n >= 4112 && n < NPAD) g_ball[n] = 0.f;
}
__global__ void wb_rows_kernel(const float* __restrict__ wfw, const float* __restrict__ wiw) {
    int i16 = blockIdx.y;
    int d = blockIdx.x * 256 + threadIdx.x;
    int g = i16 >> 3, i = i16 & 7;
    const float* ww = g ? wiw : wfw;
    float s = 0.f;
    for (int j = 0; j < 1024; j++)
        s += __ldg(&ww[i * 1024 + j]) * g_Wall[(size_t)(g * 1024 + j) * DD + d];
    g_Wall[(size_t)(4096 + i16) * DD + d] = s;
}
__global__ void bias_wb_kernel(const float* __restrict__ wfw, const float* __restrict__ wiw) {
    int w = threadIdx.x >> 5, lane = threadIdx.x & 31;
    if (w >= 16) return;
    int g = w >> 3, i = w & 7;
    const float* ww = g ? wiw : wfw;
    const float* bb = g_ball + g * 1024;
    float s = 0.f;
    for (int j = lane; j < 1024; j += 32) s += ww[i * 1024 + j] * bb[j];
#pragma unroll
    for (int o = 16; o > 0; o >>= 1) s += __shfl_xor_sync(0xFFFFFFFF, s, o);
    if (lane == 0) g_ball[4096 + w] = s;
}
// Bp[n][k] = fp16(Wall[n][k]), K-contiguous [Wx|Wh]
__global__ void bsplit_kernel() {
    size_t idx = (size_t)blockIdx.x * blockDim.x + threadIdx.x;
    if (idx >= (size_t)NPAD * 2048) return;
    int n = (int)(idx / 2048), c = (int)(idx % 2048);
    float v = (n < NC) ? g_Wall[(size_t)n * DD + c] : 0.f;
    g_Bp[idx] = __float2half(v);
}
__global__ void xprep_kernel(const float* __restrict__ X) {
    size_t idx = (size_t)blockIdx.x * blockDim.x + threadIdx.x;
    if (idx < (size_t)T_STEPS * BB * 1024)
        g_Xp[idx] = __float2half(X[idx]);
}

__global__ void tail_kernel(float* __restrict__ out) {
    int idx = blockIdx.x * blockDim.x + threadIdx.x;
    if (idx < BB * HH) {
        out[(size_t)T_STEPS * BB * HH + idx] = out[(size_t)(T_STEPS - 1) * BB * HH + idx];
        out[(size_t)T_STEPS * BB * HH + BB * HH + idx] =
            g_CXT[(size_t)(idx & 1023) * BB + (idx >> 10)];
    }
}

// ============================================================
// host
// ============================================================
extern "C" void kernel_launch(void* const* d_in, const int* in_sizes, int n_in,
                              void* d_out, int out_size)
{
    const float* X    = (const float*)d_in[0];
    const float* Wq   = (const float*)d_in[1];
    const float* bq   = (const float*)d_in[2];
    const float* encf = (const float*)d_in[3];
    const float* wfw  = (const float*)d_in[4];
    const float* wfb  = (const float*)d_in[5];
    const float* enci = (const float*)d_in[6];
    const float* wiw  = (const float*)d_in[7];
    const float* wib  = (const float*)d_in[8];
    const float* Wu   = (const float*)d_in[9];
    const float* bu   = (const float*)d_in[10];
    const float* Wo   = (const float*)d_in[11];
    const float* bo   = (const float*)d_in[12];
    float* out = (float*)d_out;

    float* Wall = nullptr; cudaGetSymbolAddress((void**)&Wall, g_Wall);

    static bool attr_done = false;
    if (!attr_done) {
        cudaFuncSetAttribute(persist_kernel, cudaFuncAttributeMaxDynamicSharedMemorySize, GSMEM);
        attr_done = true;
    }

    // ---- prep ----
    zero_cx_kernel<<<(HH * BB + 255) / 256, 256>>>();
    zero_hp_kernel<<<(BB * 1024 + 255) / 256, 256>>>();
    {
        size_t total = (size_t)2 * 1024 * DD;
        copy_wuwo_kernel<<<(unsigned)((total + 255) / 256), 256>>>(Wu, Wo);
    }
    bias_enc_kernel<<<256, 256>>>(encf, enci, bq);
    bias_copy_kernel<<<9, 256>>>(bu, bo);
    gemm_generic<<<dim3((DD + BN - 1) / BN, (1024 + BM - 1) / BM), 256>>>(
        encf, 1024, Wq, 1, DD, Wall, DD, 1024, DD, 1024);
    gemm_generic<<<dim3((DD + BN - 1) / BN, (1024 + BM - 1) / BM), 256>>>(
        enci, 1024, Wq, 1, DD, Wall + (size_t)1024 * DD, DD, 1024, DD, 1024);
    wb_rows_kernel<<<dim3(8, 16), 256>>>(wfw, wiw);
    bias_wb_kernel<<<1, 512>>>(wfw, wiw);
    {
        size_t total = (size_t)NPAD * 2048;
        bsplit_kernel<<<(unsigned)((total + 255) / 256), 256>>>();
    }
    {
        size_t total = (size_t)T_STEPS * BB * 1024;
        xprep_kernel<<<(unsigned)((total + 255) / 256), 256>>>(X);
    }

    // ---- recurrence: ONE persistent kernel, one fused GEMM per step ----
    dim3 grid_step(33, 4);   // 132 CTAs, all resident
    persist_kernel<<<grid_step, 384, GSMEM>>>(out, wfw, wfb, wiw, wib);

    tail_kernel<<<(BB * HH + 255) / 256, 256>>>(out);
}

// round 13
// speedup vs baseline: 1.2337x; 1.2337x over previous
#include <cuda_runtime.h>
#include <cuda.h>
#include <cuda_fp16.h>
#include <math.h>
#include <stdint.h>

// Problem dims
#define T_STEPS 128
#define BB      256
#define DIN     1024
#define HH      1024
#define NQ      8
#define DD      2048
#define NC      4112          // zf|zi|g|o|basef(8)|basei(8)
#define NPAD    4224          // 33 tiles of 128
#define NCTA    132

// ---------------- persistent device scratch ----------------
__device__ float g_Wall[(size_t)NC * DD];
__device__ float g_ball[NPAD];
__device__ __align__(256) __half g_Bpx[(size_t)NPAD * 1024];        // Wx fp16
__device__ __align__(256) __half g_Bph[(size_t)NPAD * 1024];        // Wh fp16
__device__ __align__(256) __half g_Xp[(size_t)T_STEPS * BB * 1024]; // fp16(X)
__device__ __align__(256) __half g_Hp[(size_t)BB * 1024];           // fp16(hx)
__device__ __align__(256) __half g_encf16[1024 * 1024];
__device__ __align__(256) __half g_enci16[1024 * 1024];
__device__ __align__(256) __half g_WqT[2048 * 1024];                // Wq^T fp16 [d][q]
__device__ float g_CXall[(size_t)T_STEPS * NPAD * BB];              // X-part C^T per t (+bias)
__device__ float g_CTh[(size_t)NPAD * BB];                          // H-part C^T
__device__ float g_CXT[HH * BB];                                    // cell state [h][b]
__device__ unsigned long long g_bar = 0;

// ============================================================
// common mma helpers
// ============================================================
__device__ __forceinline__ uint32_t smem_u32(const void* p) {
    uint32_t a;
    asm("{ .reg .u64 t; cvta.to.shared.u64 t, %1; cvt.u32.u64 %0, t; }" : "=r"(a) : "l"(p));
    return a;
}
__device__ __forceinline__ void cp_async16(uint32_t dst, const void* src) {
    asm volatile("cp.async.cg.shared.global [%0], [%1], 16;" :: "r"(dst), "l"(src));
}
__device__ __forceinline__ void ldmatrix_x4(uint32_t& r0, uint32_t& r1,
                                            uint32_t& r2, uint32_t& r3, uint32_t a) {
    asm volatile("ldmatrix.sync.aligned.m8n8.x4.shared.b16 {%0,%1,%2,%3}, [%4];"
                 : "=r"(r0), "=r"(r1), "=r"(r2), "=r"(r3) : "r"(a));
}
__device__ __forceinline__ void mma_f16(float* c, const uint32_t* a,
                                        uint32_t b0, uint32_t b1) {
    asm volatile("mma.sync.aligned.m16n8k16.row.col.f32.f16.f16.f32 "
                 "{%0,%1,%2,%3}, {%4,%5,%6,%7}, {%8,%9}, {%0,%1,%2,%3};"
                 : "+f"(c[0]), "+f"(c[1]), "+f"(c[2]), "+f"(c[3])
                 : "r"(a[0]), "r"(a[1]), "r"(a[2]), "r"(a[3]), "r"(b0), "r"(b1));
}
__device__ __forceinline__ float sigf(float x) {
    float e = __expf(-x);
    return __fdividef(1.f, 1.f + e);
}

// ============================================================
// Loop H-GEMM: block 64(M)x128(N), 8 warps (2Mx4N), warp 32x32,
// K=1024, BK=32, 3-stage. (R11-validated)
// ============================================================
#define APITCH  40
#define A_ST    (64 * APITCH * 2)        // 5120
#define B_ST    (128 * APITCH * 2)       // 10240
#define STG_B   (A_ST + B_ST)            // 15360
#define GSMEM   (3 * STG_B)              // 46080
#define NTL     32

#define GBAR_WARPS() asm volatile("bar.sync 1, 256;" ::: "memory")

__device__ __forceinline__ void gemm64(const __half* __restrict__ Asrc,
                                       const __half* __restrict__ Bsrc,
                                       float* __restrict__ Cdst,
                                       int m0, int n0, uint32_t sb, int tid)
{
    const int lane = tid & 31, wid = tid >> 5;
    const int wm = wid & 1, wn = wid >> 1;

    const int arow = tid >> 2, ach = tid & 3;
    const __half* gA = Asrc + (size_t)(m0 + arow) * 1024 + ach * 8;
    const uint32_t daB = sb + (arow * APITCH + ach * 8) * 2;
    const int brow = tid >> 1, bch = tid & 1;
    const __half* gB = Bsrc + (size_t)(n0 + brow) * 1024 + bch * 16;
    const uint32_t dbB = sb + A_ST + (brow * APITCH + bch * 16) * 2;

    float acc[2][4][4];
#pragma unroll
    for (int i = 0; i < 2; i++)
#pragma unroll
        for (int j = 0; j < 4; j++)
#pragma unroll
            for (int r = 0; r < 4; r++) acc[i][j][r] = 0.f;

    const uint32_t aA0 = sb + ((wm * 32 + (lane & 15)) * APITCH + (lane >> 4) * 8) * 2;
    const int brl = wn * 32 + (lane & 7) + ((lane >> 4) << 3);
    const uint32_t bA0 = sb + A_ST + (brl * APITCH + ((lane >> 3) & 1) * 8) * 2;

    auto issue = [&](int kt, int st) {
        cp_async16(daB + st * STG_B, gA + kt * 32);
        const uint32_t db = dbB + st * STG_B;
        const __half* gb = gB + kt * 32;
        cp_async16(db, gb);
        cp_async16(db + 16, gb + 8);
    };

#pragma unroll
    for (int s = 0; s < 2; s++) {
        issue(s, s);
        asm volatile("cp.async.commit_group;");
    }

    for (int kt = 0; kt < NTL; kt++) {
        asm volatile("cp.async.wait_group 1;");
        GBAR_WARPS();
        if (kt + 2 < NTL) issue(kt + 2, (kt + 2) % 3);
        asm volatile("cp.async.commit_group;");

        const int st = kt % 3;
        const uint32_t aB = aA0 + st * STG_B;
        const uint32_t bB = bA0 + st * STG_B;
#pragma unroll
        for (int kk = 0; kk < 2; kk++) {
            uint32_t a[2][4], b[2][4];
#pragma unroll
            for (int mf = 0; mf < 2; mf++)
                ldmatrix_x4(a[mf][0], a[mf][1], a[mf][2], a[mf][3],
                            aB + (mf * 16 * APITCH + kk * 16) * 2);
#pragma unroll
            for (int nf = 0; nf < 2; nf++)
                ldmatrix_x4(b[nf][0], b[nf][1], b[nf][2], b[nf][3],
                            bB + (nf * 16 * APITCH + kk * 16) * 2);
#pragma unroll
            for (int mf = 0; mf < 2; mf++)
#pragma unroll
                for (int nf = 0; nf < 2; nf++) {
                    mma_f16(acc[mf][nf * 2 + 0], a[mf], b[nf][0], b[nf][1]);
                    mma_f16(acc[mf][nf * 2 + 1], a[mf], b[nf][2], b[nf][3]);
                }
        }
    }

#pragma unroll
    for (int mf = 0; mf < 2; mf++) {
        const int mb = m0 + wm * 32 + mf * 16 + (lane >> 2);
#pragma unroll
        for (int j = 0; j < 4; j++) {
            const int nb = n0 + wn * 32 + j * 8 + 2 * (lane & 3);
            Cdst[(size_t)nb * BB + mb]           = acc[mf][j][0];
            Cdst[(size_t)(nb + 1) * BB + mb]     = acc[mf][j][1];
            Cdst[(size_t)nb * BB + mb + 8]       = acc[mf][j][2];
            Cdst[(size_t)(nb + 1) * BB + mb + 8] = acc[mf][j][3];
        }
    }
}

__device__ __forceinline__ void grid_bar(int tid) {
    __syncthreads();
    if (tid == 0) {
        __threadfence();
        unsigned long long t0 = atomicAdd(&g_bar, 1ULL);
        unsigned long long tgt = (t0 / (unsigned long long)NCTA + 1ULL) * (unsigned long long)NCTA;
        while (*((volatile unsigned long long*)&g_bar) < tgt) { __nanosleep(32); }
        __threadfence();
    }
    __syncthreads();
}

// ============================================================
// Persistent loop kernel: H-GEMM + elem per step
// ============================================================
__global__ __launch_bounds__(384, 1) void persist_kernel(
    float* __restrict__ out,
    const float* __restrict__ wfw, const float* __restrict__ wfb,
    const float* __restrict__ wiw, const float* __restrict__ wib)
{
    extern __shared__ __align__(16) char smraw[];
    const uint32_t sb = smem_u32(smraw);
    const int tid = threadIdx.x;
    const int n0 = blockIdx.x * 128, m0 = blockIdx.y * 64;
    const int cta = blockIdx.y * 33 + blockIdx.x;

    for (int t = 0; t < T_STEPS; t++) {
        if (tid < 256)
            gemm64(g_Hp, g_Bph, g_CTh, m0, n0, sb, tid);
        grid_bar(tid);

        const float* cth = g_CTh;
        const float* ctx = g_CXall + (size_t)t * NPAD * BB;
        float* out_t = out + (size_t)t * BB * HH;
#pragma unroll 1
        for (int k = 0; k < 6; k++) {
            int id = cta * 384 + tid + k * (NCTA * 384);
            if (id >= BB * HH) break;
            int h = id >> 8, b = id & 255;
            auto rd = [&](int n) {
                size_t p = (size_t)n * BB + b;
                return cth[p] + ctx[p];
            };
            float f_pre, i_pre;
            if (h < NQ) {
                float df[NQ], di[NQ];
                f_pre = 0.f; i_pre = 0.f;
#pragma unroll
                for (int i = 0; i < NQ; i++) {
                    float dot = rd(4096 + i) + __ldg(&wfb[i]);
#pragma unroll
                    for (int kk = 0; kk < NQ; kk++)
                        if (kk < i) dot += df[kk] * __ldg(&wfw[i * 1024 + kk]);
                    float v = tanhf(dot);
                    df[i] = v - rd(i);
                    if (i == h) f_pre = v;
                }
#pragma unroll
                for (int i = 0; i < NQ; i++) {
                    float dot = rd(4104 + i) + __ldg(&wib[i]);
#pragma unroll
                    for (int kk = 0; kk < NQ; kk++)
                        if (kk < i) dot += di[kk] * __ldg(&wiw[i * 1024 + kk]);
                    float v = tanhf(dot);
                    di[i] = v - rd(1024 + i);
                    if (i == h) i_pre = v;
                }
            } else {
                f_pre = rd(h);
                i_pre = rd(1024 + h);
            }
            const float gg = tanhf(rd(2048 + h));
            const float o  = sigf(rd(3072 + h));
            const size_t p = (size_t)h * BB + b;
            const float c = sigf(f_pre) * g_CXT[p] + sigf(i_pre) * gg;
            g_CXT[p] = c;
            const float hv = o * tanhf(c);
            out_t[(size_t)b * HH + h] = hv;
            g_Hp[(size_t)b * 1024 + h] = __float2half(hv);
        }
        grid_bar(tid);
    }
}

// ============================================================
// Big-GEMM core: block 256(M)x128(N), 8 warps (4Mx2N), warp 64x64,
// K=1024, BK=32, 4-stage. (R8-validated geometry)
// ============================================================
#define XAP     40
#define XP_AST  (256 * XAP * 2)          // 20480
#define XP_BST  (128 * XAP * 2)          // 10240
#define XP_STG  (XP_AST + XP_BST)        // 30720
#define XP_SMEM (4 * XP_STG)             // 122880

// macro-free shared mainloop via inline function computing acc
struct Acc256 { float v[4][8][4]; };

__device__ __forceinline__ void big_mainloop(const __half* __restrict__ Asrc,
                                             const __half* __restrict__ Bsrc,
                                             int m0, int n0, uint32_t sb, int tid,
                                             Acc256& A)
{
    const int lane = tid & 31, wid = tid >> 5;
    const int wm = wid >> 1, wn = wid & 1;

    const __half* gA = Asrc + (size_t)(m0 + tid) * 1024;     // 1 thread/row, 64B
    const uint32_t daB = sb + (tid * XAP) * 2;
    const int brow = tid >> 1, bch = tid & 1;
    const __half* gB = Bsrc + (size_t)(n0 + brow) * 1024 + bch * 16;
    const uint32_t dbB = sb + XP_AST + (brow * XAP + bch * 16) * 2;

    auto issue = [&](int kt, int st) {
        const uint32_t da = daB + st * XP_STG;
        const __half* ga = gA + kt * 32;
#pragma unroll
        for (int j = 0; j < 4; j++) cp_async16(da + j * 16, ga + j * 8);
        const uint32_t db = dbB + st * XP_STG;
        const __half* gb = gB + kt * 32;
        cp_async16(db, gb);
        cp_async16(db + 16, gb + 8);
    };

#pragma unroll
    for (int i = 0; i < 4; i++)
#pragma unroll
        for (int j = 0; j < 8; j++)
#pragma unroll
            for (int r = 0; r < 4; r++) A.v[i][j][r] = 0.f;

    const uint32_t aA0 = sb + ((wm * 64 + (lane & 15)) * XAP + (lane >> 4) * 8) * 2;
    const int brl = wn * 64 + (lane & 7) + ((lane >> 4) << 3);
    const uint32_t bA0 = sb + XP_AST + (brl * XAP + ((lane >> 3) & 1) * 8) * 2;

#pragma unroll
    for (int s = 0; s < 3; s++) {
        issue(s, s);
        asm volatile("cp.async.commit_group;");
    }

    for (int kt = 0; kt < 32; kt++) {
        asm volatile("cp.async.wait_group 2;");
        __syncthreads();
        if (kt + 3 < 32) issue(kt + 3, (kt + 3) & 3);
        asm volatile("cp.async.commit_group;");

        const int st = kt & 3;
        const uint32_t aB = aA0 + st * XP_STG;
        const uint32_t bB = bA0 + st * XP_STG;
#pragma unroll
        for (int kk = 0; kk < 2; kk++) {
            uint32_t a[4][4], b[4][4];
#pragma unroll
            for (int mf = 0; mf < 4; mf++)
                ldmatrix_x4(a[mf][0], a[mf][1], a[mf][2], a[mf][3],
                            aB + (mf * 16 * XAP + kk * 16) * 2);
#pragma unroll
            for (int nf = 0; nf < 4; nf++)
                ldmatrix_x4(b[nf][0], b[nf][1], b[nf][2], b[nf][3],
                            bB + (nf * 16 * XAP + kk * 16) * 2);
#pragma unroll
            for (int mf = 0; mf < 4; mf++)
#pragma unroll
                for (int nf = 0; nf < 4; nf++) {
                    mma_f16(A.v[mf][nf * 2 + 0], a[mf], b[nf][0], b[nf][1]);
                    mma_f16(A.v[mf][nf * 2 + 1], a[mf], b[nf][2], b[nf][3]);
                }
        }
    }
}

// X precompute: CXall[t][n][b] = X[t]@Wx^T + bias.  grid (33, 128)
__global__ __launch_bounds__(256, 1) void xpre_kernel()
{
    extern __shared__ __align__(16) char smraw[];
    const uint32_t sb = smem_u32(smraw);
    const int tid = threadIdx.x, lane = tid & 31, wid = tid >> 5;
    const int wm = wid >> 1, wn = wid & 1;
    const int n0 = blockIdx.x * 128;
    const int m0 = blockIdx.y * 256;         // m = t*256 + b -> t = blockIdx.y

    Acc256 A;
    big_mainloop(g_Xp, g_Bpx, m0, n0, sb, tid, A);

    float* ct = g_CXall + (size_t)blockIdx.y * NPAD * BB;
#pragma unroll
    for (int mf = 0; mf < 4; mf++) {
        const int mb = wm * 64 + mf * 16 + (lane >> 2);   // = batch b
#pragma unroll
        for (int q = 0; q < 8; q++) {
            const int nb = n0 + wn * 64 + q * 8 + 2 * (lane & 3);
            const float b0 = __ldg(&g_ball[nb]), b1 = __ldg(&g_ball[nb + 1]);
            ct[(size_t)nb * BB + mb]           = A.v[mf][q][0] + b0;
            ct[(size_t)(nb + 1) * BB + mb]     = A.v[mf][q][1] + b1;
            ct[(size_t)nb * BB + mb + 8]       = A.v[mf][q][2] + b0;
            ct[(size_t)(nb + 1) * BB + mb + 8] = A.v[mf][q][3] + b1;
        }
    }
}

// prep: Wall rows [z*1024, z*1024+1024) = enc_z @ Wq  (fp16 in, f32 out)
// grid (16, 4, 2)
__global__ __launch_bounds__(256, 1) void prep_mma_kernel()
{
    extern __shared__ __align__(16) char smraw[];
    const uint32_t sb = smem_u32(smraw);
    const int tid = threadIdx.x, lane = tid & 31, wid = tid >> 5;
    const int wm = wid >> 1, wn = wid & 1;
    const int n0 = blockIdx.x * 128;
    const int m0 = blockIdx.y * 256;
    const int z  = blockIdx.z;

    Acc256 A;
    big_mainloop(z ? g_enci16 : g_encf16, g_WqT, m0, n0, sb, tid, A);

    float* Wdst = g_Wall + (size_t)(z * 1024 + m0) * DD;
#pragma unroll
    for (int mf = 0; mf < 4; mf++) {
        const int mb = wm * 64 + mf * 16 + (lane >> 2);
#pragma unroll
        for (int q = 0; q < 8; q++) {
            const int nb = n0 + wn * 64 + q * 8 + 2 * (lane & 3);
            Wdst[(size_t)mb * DD + nb]           = A.v[mf][q][0];
            Wdst[(size_t)mb * DD + nb + 1]       = A.v[mf][q][1];
            Wdst[(size_t)(mb + 8) * DD + nb]     = A.v[mf][q][2];
            Wdst[(size_t)(mb + 8) * DD + nb + 1] = A.v[mf][q][3];
        }
    }
}

// ============================================================
// small prep kernels
// ============================================================
__global__ void zero_cx_kernel() {
    int idx = blockIdx.x * blockDim.x + threadIdx.x;
    if (idx < HH * BB) g_CXT[idx] = 0.f;
}
__global__ void zero_hp_kernel() {
    int idx = blockIdx.x * blockDim.x + threadIdx.x;
    if (idx < BB * 1024) g_Hp[idx] = __float2half(0.f);
}
__global__ void copy_wuwo_kernel(const float* __restrict__ Wu, const float* __restrict__ Wo) {
    size_t idx = (size_t)blockIdx.x * blockDim.x + threadIdx.x;
    size_t total = (size_t)2 * 1024 * DD;
    if (idx < total) {
        float v = (idx < (size_t)1024 * DD) ? Wu[idx] : Wo[idx - (size_t)1024 * DD];
        g_Wall[(size_t)2048 * DD + idx] = v;
    }
}
__global__ void enc16_kernel(const float* __restrict__ encf, const float* __restrict__ enci) {
    int idx = blockIdx.x * blockDim.x + threadIdx.x;
    if (idx < 1024 * 1024) {
        g_encf16[idx] = __float2half(encf[idx]);
        g_enci16[idx] = __float2half(enci[idx]);
    }
}
// WqT[d][q] = fp16(Wq[q][d]); Wq is [1024][2048]
__global__ void wqt_kernel(const float* __restrict__ Wq) {
    __shared__ float tile[32][33];
    int dx = blockIdx.x * 32, qy = blockIdx.y * 32;
    int tx = threadIdx.x, ty = threadIdx.y;
#pragma unroll
    for (int r = 0; r < 4; r++)
        tile[ty + r * 8][tx] = Wq[(size_t)(qy + ty + r * 8) * 2048 + dx + tx];
    __syncthreads();
#pragma unroll
    for (int r = 0; r < 4; r++)
        g_WqT[(size_t)(dx + ty + r * 8) * 1024 + qy + tx] =
            __float2half(tile[tx][ty + r * 8]);
}
__global__ void bias_enc_kernel(const float* __restrict__ encf, const float* __restrict__ enci,
                                const float* __restrict__ bq)
{
    int w = (blockIdx.x * blockDim.x + threadIdx.x) >> 5;
    int lane = threadIdx.x & 31;
    if (w >= 2048) return;
    const float* enc = (w < 1024) ? encf : enci;
    int row = w & 1023;
    float s = 0.f;
    for (int j = lane; j < 1024; j += 32) s += enc[row * 1024 + j] * bq[j];
#pragma unroll
    for (int o = 16; o > 0; o >>= 1) s += __shfl_xor_sync(0xFFFFFFFF, s, o);
    if (lane == 0) g_ball[w] = s;
}
__global__ void bias_copy_kernel(const float* __restrict__ bu, const float* __restrict__ bo) {
    int n = 2048 + blockIdx.x * blockDim.x + threadIdx.x;
    if (n < 3072) g_ball[n] = bu[n - 2048];
    else if (n < 4096) g_ball[n] = bo[n - 3072];
    else if (n >= 4112 && n < NPAD) g_ball[n] = 0.f;
}
__global__ void wb_rows_kernel(const float* __restrict__ wfw, const float* __restrict__ wiw) {
    int i16 = blockIdx.y;
    int d = blockIdx.x * 256 + threadIdx.x;
    int g = i16 >> 3, i = i16 & 7;
    const float* ww = g ? wiw : wfw;
    float s = 0.f;
    for (int j = 0; j < 1024; j++)
        s += __ldg(&ww[i * 1024 + j]) * g_Wall[(size_t)(g * 1024 + j) * DD + d];
    g_Wall[(size_t)(4096 + i16) * DD + d] = s;
}
__global__ void bias_wb_kernel(const float* __restrict__ wfw, const float* __restrict__ wiw) {
    int w = threadIdx.x >> 5, lane = threadIdx.x & 31;
    if (w >= 16) return;
    int g = w >> 3, i = w & 7;
    const float* ww = g ? wiw : wfw;
    const float* bb = g_ball + g * 1024;
    float s = 0.f;
    for (int j = lane; j < 1024; j += 32) s += ww[i * 1024 + j] * bb[j];
#pragma unroll
    for (int o = 16; o > 0; o >>= 1) s += __shfl_xor_sync(0xFFFFFFFF, s, o);
    if (lane == 0) g_ball[4096 + w] = s;
}
__global__ void bsplit_kernel() {
    size_t idx = (size_t)blockIdx.x * blockDim.x + threadIdx.x;
    if (idx >= (size_t)NPAD * 2048) return;
    int n = (int)(idx / 2048), c = (int)(idx % 2048);
    float v = (n < NC) ? g_Wall[(size_t)n * DD + c] : 0.f;
    if (c < 1024) g_Bpx[(size_t)n * 1024 + c] = __float2half(v);
    else          g_Bph[(size_t)n * 1024 + (c - 1024)] = __float2half(v);
}
__global__ void xprep_kernel(const float* __restrict__ X) {
    size_t idx = (size_t)blockIdx.x * blockDim.x + threadIdx.x;
    if (idx < (size_t)T_STEPS * BB * 1024)
        g_Xp[idx] = __float2half(X[idx]);
}
__global__ void tail_kernel(float* __restrict__ out) {
    int idx = blockIdx.x * blockDim.x + threadIdx.x;
    if (idx < BB * HH) {
        out[(size_t)T_STEPS * BB * HH + idx] = out[(size_t)(T_STEPS - 1) * BB * HH + idx];
        out[(size_t)T_STEPS * BB * HH + BB * HH + idx] =
            g_CXT[(size_t)(idx & 1023) * BB + (idx >> 10)];
    }
}

// ============================================================
// host
// ============================================================
extern "C" void kernel_launch(void* const* d_in, const int* in_sizes, int n_in,
                              void* d_out, int out_size)
{
    const float* X    = (const float*)d_in[0];
    const float* Wq   = (const float*)d_in[1];
    const float* bq   = (const float*)d_in[2];
    const float* encf = (const float*)d_in[3];
    const float* wfw  = (const float*)d_in[4];
    const float* wfb  = (const float*)d_in[5];
    const float* enci = (const float*)d_in[6];
    const float* wiw  = (const float*)d_in[7];
    const float* wib  = (const float*)d_in[8];
    const float* Wu   = (const float*)d_in[9];
    const float* bu   = (const float*)d_in[10];
    const float* Wo   = (const float*)d_in[11];
    const float* bo   = (const float*)d_in[12];
    float* out = (float*)d_out;

    static bool attr_done = false;
    if (!attr_done) {
        cudaFuncSetAttribute(persist_kernel, cudaFuncAttributeMaxDynamicSharedMemorySize, GSMEM);
        cudaFuncSetAttribute(xpre_kernel, cudaFuncAttributeMaxDynamicSharedMemorySize, XP_SMEM);
        cudaFuncSetAttribute(prep_mma_kernel, cudaFuncAttributeMaxDynamicSharedMemorySize, XP_SMEM);
        attr_done = true;
    }

    // ---- prep ----
    zero_cx_kernel<<<(HH * BB + 255) / 256, 256>>>();
    zero_hp_kernel<<<(BB * 1024 + 255) / 256, 256>>>();
    {
        size_t total = (size_t)2 * 1024 * DD;
        copy_wuwo_kernel<<<(unsigned)((total + 255) / 256), 256>>>(Wu, Wo);
    }
    enc16_kernel<<<(1024 * 1024 + 255) / 256, 256>>>(encf, enci);
    wqt_kernel<<<dim3(64, 32), dim3(32, 8)>>>(Wq);
    prep_mma_kernel<<<dim3(16, 4, 2), 256, XP_SMEM>>>();
    bias_enc_kernel<<<256, 256>>>(encf, enci, bq);
    bias_copy_kernel<<<9, 256>>>(bu, bo);
    wb_rows_kernel<<<dim3(8, 16), 256>>>(wfw, wiw);
    bias_wb_kernel<<<1, 512>>>(wfw, wiw);
    {
        size_t total = (size_t)NPAD * 2048;
        bsplit_kernel<<<(unsigned)((total + 255) / 256), 256>>>();
    }
    {
        size_t total = (size_t)T_STEPS * BB * 1024;
        xprep_kernel<<<(unsigned)((total + 255) / 256), 256>>>(X);
    }

    // ---- X precompute: one big GEMM for all timesteps ----
    xpre_kernel<<<dim3(33, T_STEPS), 256, XP_SMEM>>>();

    // ---- recurrence: persistent H-GEMM + elem ----
    dim3 grid_step(33, 4);   // 132 CTAs, all resident
    persist_kernel<<<grid_step, 384, GSMEM>>>(out, wfw, wfb, wiw, wib);

    tail_kernel<<<(BB * HH + 255) / 256, 256>>>(out);
}